// round 9
// baseline (speedup 1.0000x reference)
#include <cuda_runtime.h>
#include <cuda_bf16.h>
#include <cstdint>
#include <cstddef>

// Problem constants
#define BB   64
#define NN   4096
#define CC   64
#define OUTF 64
#define K2   4
#define TM   64                        // sites per tile (GEMM M)
#define KDIM 256                       // GEMM K = K2*CC
#define NTILES 4096                    // BB * NN / TM
#define GRID 148
#define NTHREADS 512

#define ASTRB 528                      // row stride bytes (264 bf16; %32 words == 4 -> ldmatrix conflict-free)
#define ATILE (TM * ASTRB)             // 33792 bytes per (hi or lo) A tile
#define ASTAGE (2 * ATILE)             // 67584 bytes per stage (hi + lo)

// smem layout (bytes)
#define SM_BIAS 0                      // 64 floats
#define SM_BHI  512                    // 64 rows * 528B
#define SM_BLO  (SM_BHI + OUTF * ASTRB)
#define SM_A    (SM_BLO + OUTF * ASTRB)     // 2 stages: [stage][hi|lo][64][528]
#define SM_TOTAL (SM_A + 2 * ASTAGE)        // 203264 bytes

__device__ __forceinline__ uint32_t smem_u32(const void* p) {
    uint32_t a;
    asm("{ .reg .u64 t; cvta.to.shared.u64 t, %1; cvt.u32.u64 %0, t; }" : "=r"(a) : "l"(p));
    return a;
}
__device__ __forceinline__ void ldsm_x4(uint32_t& r0, uint32_t& r1, uint32_t& r2, uint32_t& r3,
                                        uint32_t addr) {
    asm volatile("ldmatrix.sync.aligned.m8n8.x4.shared.b16 {%0,%1,%2,%3}, [%4];"
                 : "=r"(r0), "=r"(r1), "=r"(r2), "=r"(r3) : "r"(addr));
}
__device__ __forceinline__ void mma_bf16(float* acc, const uint32_t* a, const uint32_t* b) {
    asm volatile(
        "mma.sync.aligned.m16n8k16.row.col.f32.bf16.bf16.f32 "
        "{%0,%1,%2,%3}, {%4,%5,%6,%7}, {%8,%9}, {%0,%1,%2,%3};"
        : "+f"(acc[0]), "+f"(acc[1]), "+f"(acc[2]), "+f"(acc[3])
        : "r"(a[0]), "r"(a[1]), "r"(a[2]), "r"(a[3]), "r"(b[0]), "r"(b[1]));
}
__device__ __forceinline__ uint32_t pack_bf2(__nv_bfloat16 a, __nv_bfloat16 b) {
    __nv_bfloat162 t = __halves2bfloat162(a, b);
    uint32_t u;
    memcpy(&u, &t, 4);
    return u;
}

__global__ __launch_bounds__(NTHREADS, 1)
void conv_mma_pipe_kernel(const float* __restrict__ x,
                          const float* __restrict__ W,
                          const float* __restrict__ bias,
                          const int*   __restrict__ kernel2,
                          float*       __restrict__ out)
{
    extern __shared__ char smem[];
    const uint32_t sbase = smem_u32(smem);
    const int tid  = threadIdx.x;
    const int wid  = tid >> 5;
    const int lane = tid & 31;
    const int wm   = wid & 3;          // warp M index: 4 groups of 16 rows
    const int wn   = wid >> 2;         // warp N index: 4 groups of 16 cols
    const int l16  = lane & 15;        // float4 slot within a gathered row
    const int rsub = lane >> 4;        // which of 2 rows this half-warp owns

    float* bias_s = reinterpret_cast<float*>(smem + SM_BIAS);
    if (tid < OUTF) bias_s[tid] = bias[tid];

    // ---- One-time: W split -> B_hi/B_lo smem, layout [o][kc] bf16, 528B stride ----
    for (int idx = tid; idx < OUTF * (KDIM / 2); idx += NTHREADS) {   // 8192 pairs
        const int o   = idx >> 7;
        const int kc0 = (idx & 127) << 1;
        const int k   = kc0 >> 6;
        const int c0  = kc0 & 63;
        const float* wp = W + k * (CC * OUTF) + c0 * OUTF + o;
        const float w0 = wp[0];
        const float w1 = wp[OUTF];
        const __nv_bfloat16 h0 = __float2bfloat16(w0);
        const __nv_bfloat16 h1 = __float2bfloat16(w1);
        const __nv_bfloat16 l0 = __float2bfloat16(w0 - __bfloat162float(h0));
        const __nv_bfloat16 l1 = __float2bfloat16(w1 - __bfloat162float(h1));
        const int off = o * ASTRB + kc0 * 2;
        *reinterpret_cast<uint32_t*>(smem + SM_BHI + off) = pack_bf2(h0, h1);
        *reinterpret_cast<uint32_t*>(smem + SM_BLO + off) = pack_bf2(l0, l1);
    }

    // ---- Tile-invariant ldmatrix per-lane addresses ----
    const int m  = lane >> 3;          // matrix index 0..3
    const int l7 = lane & 7;           // row-within-8
    // A x4 frags (m16 x k16): (r0-7,k0-7),(r8-15,k0-7),(r0-7,k8-15),(r8-15,k8-15)
    const uint32_t aoff = (uint32_t)((wm * 16 + ((m & 1) << 3) + l7) * ASTRB + ((m >> 1) << 4));
    // B x4 frags (n16 x k16): (n0-7,k0-7),(n0-7,k8-15),(n8-15,k0-7),(n8-15,k8-15)
    const uint32_t boff = (uint32_t)((wn * 16 + ((m >> 1) << 3) + l7) * ASTRB + ((m & 1) << 4));
    const uint32_t bhi = sbase + SM_BHI + boff;
    const uint32_t blo = sbase + SM_BLO + boff;

    // Per-thread gather geometry: 8 passes, row rid = wid*2 + rsub + pass*32 (0..255)
    // rid -> s = rid>>2, k = rid&3; STS offset = s*528 + k*128 + l16*8
    const int rid0 = wid * 2 + rsub;

    // ---- Prologue: gather tile blockIdx.x into stage 0 ----
    int t = blockIdx.x;
    {
        const int b  = t >> 6;
        const int n0 = (t & 63) * TM;
        const float* xb = x + (size_t)b * NN * CC + l16 * 4;
        int gi[8];
        #pragma unroll
        for (int p = 0; p < 8; ++p)
            gi[p] = __ldg(kernel2 + n0 * K2 + rid0 + p * 32);
        #pragma unroll
        for (int p = 0; p < 8; ++p) {
            const float4 v = *reinterpret_cast<const float4*>(xb + (size_t)gi[p] * CC);
            const int rid = rid0 + p * 32;
            const int off = (rid >> 2) * ASTRB + (rid & 3) * 128 + l16 * 8;
            const __nv_bfloat16 h0 = __float2bfloat16(v.x);
            const __nv_bfloat16 h1 = __float2bfloat16(v.y);
            const __nv_bfloat16 h2 = __float2bfloat16(v.z);
            const __nv_bfloat16 h3 = __float2bfloat16(v.w);
            const __nv_bfloat16 e0 = __float2bfloat16(v.x - __bfloat162float(h0));
            const __nv_bfloat16 e1 = __float2bfloat16(v.y - __bfloat162float(h1));
            const __nv_bfloat16 e2 = __float2bfloat16(v.z - __bfloat162float(h2));
            const __nv_bfloat16 e3 = __float2bfloat16(v.w - __bfloat162float(h3));
            uint2 hv, lv;
            hv.x = pack_bf2(h0, h1);  hv.y = pack_bf2(h2, h3);
            lv.x = pack_bf2(e0, e1);  lv.y = pack_bf2(e2, e3);
            *reinterpret_cast<uint2*>(smem + SM_A + off)         = hv;
            *reinterpret_cast<uint2*>(smem + SM_A + ATILE + off) = lv;
        }
    }
    __syncthreads();

    // ---- Pipelined tile loop ----
    int stage = 0;
    while (t < NTILES) {
        const int tn = t + GRID;
        const bool havenext = (tn < NTILES);

        // -- Prefetch next tile into registers (latency hidden under MMA below) --
        float4 v[8];
        if (havenext) {
            const int bn  = tn >> 6;
            const int n0n = (tn & 63) * TM;
            const float* xb = x + (size_t)bn * NN * CC + l16 * 4;
            int gi[8];
            #pragma unroll
            for (int p = 0; p < 8; ++p)
                gi[p] = __ldg(kernel2 + n0n * K2 + rid0 + p * 32);
            #pragma unroll
            for (int p = 0; p < 8; ++p)
                v[p] = *reinterpret_cast<const float4*>(xb + (size_t)gi[p] * CC);
        }

        // -- MMA on current stage: Ahi*Bhi + Ahi*Blo + Alo*Bhi --
        const uint32_t ahiS = sbase + SM_A + (uint32_t)stage * ASTAGE + aoff;
        const uint32_t aloS = ahiS + ATILE;
        float acc[2][4];
        #pragma unroll
        for (int i = 0; i < 2; ++i)
            #pragma unroll
            for (int q = 0; q < 4; ++q)
                acc[i][q] = 0.0f;

        #pragma unroll 4
        for (int ks = 0; ks < 16; ++ks) {
            const uint32_t kb = (uint32_t)ks * 32;
            uint32_t AH[4], AL[4], BH[4], BL[4];
            ldsm_x4(AH[0], AH[1], AH[2], AH[3], ahiS + kb);
            ldsm_x4(AL[0], AL[1], AL[2], AL[3], aloS + kb);
            ldsm_x4(BH[0], BH[1], BH[2], BH[3], bhi + kb);
            ldsm_x4(BL[0], BL[1], BL[2], BL[3], blo + kb);
            #pragma unroll
            for (int ni = 0; ni < 2; ++ni) {
                mma_bf16(acc[ni], AH, BH + 2 * ni);
                mma_bf16(acc[ni], AH, BL + 2 * ni);
                mma_bf16(acc[ni], AL, BH + 2 * ni);
            }
        }

        // -- Epilogue: bias + store tile t --
        {
            const int b  = t >> 6;
            const int n0 = (t & 63) * TM;
            const size_t r0 = (size_t)b * NN + n0 + wm * 16 + (lane >> 2);
            #pragma unroll
            for (int ni = 0; ni < 2; ++ni) {
                const int col = wn * 16 + ni * 8 + (lane & 3) * 2;
                const float b0 = bias_s[col];
                const float b1 = bias_s[col + 1];
                float2 v0, v1;
                v0.x = acc[ni][0] + b0;  v0.y = acc[ni][1] + b1;
                v1.x = acc[ni][2] + b0;  v1.y = acc[ni][3] + b1;
                *reinterpret_cast<float2*>(out + r0 * OUTF + col)       = v0;
                *reinterpret_cast<float2*>(out + (r0 + 8) * OUTF + col) = v1;
            }
        }

        // -- Convert + store prefetched data into the other stage --
        if (havenext) {
            char* dstA = smem + SM_A + (stage ^ 1) * ASTAGE;
            #pragma unroll
            for (int p = 0; p < 8; ++p) {
                const int rid = rid0 + p * 32;
                const int off = (rid >> 2) * ASTRB + (rid & 3) * 128 + l16 * 8;
                const __nv_bfloat16 h0 = __float2bfloat16(v[p].x);
                const __nv_bfloat16 h1 = __float2bfloat16(v[p].y);
                const __nv_bfloat16 h2 = __float2bfloat16(v[p].z);
                const __nv_bfloat16 h3 = __float2bfloat16(v[p].w);
                const __nv_bfloat16 e0 = __float2bfloat16(v[p].x - __bfloat162float(h0));
                const __nv_bfloat16 e1 = __float2bfloat16(v[p].y - __bfloat162float(h1));
                const __nv_bfloat16 e2 = __float2bfloat16(v[p].z - __bfloat162float(h2));
                const __nv_bfloat16 e3 = __float2bfloat16(v[p].w - __bfloat162float(h3));
                uint2 hv, lv;
                hv.x = pack_bf2(h0, h1);  hv.y = pack_bf2(h2, h3);
                lv.x = pack_bf2(e0, e1);  lv.y = pack_bf2(e2, e3);
                *reinterpret_cast<uint2*>(dstA + off)         = hv;
                *reinterpret_cast<uint2*>(dstA + ATILE + off) = lv;
            }
        }

        // One barrier per tile:
        //  - makes next stage's STS visible to all warps before its MMA
        //  - ensures all warps' MMA reads of `stage` finished before it is
        //    overwritten in the NEXT iteration's STS
        __syncthreads();
        t = tn;
        stage ^= 1;
    }
}

extern "C" void kernel_launch(void* const* d_in, const int* in_sizes, int n_in,
                              void* d_out, int out_size)
{
    const float* x    = (const float*)d_in[0];   // [B, N, C]
    const float* W    = (const float*)d_in[1];   // [K2, C, OUT]
    const float* bias = (const float*)d_in[2];   // [OUT]
    const int*   k2   = (const int*)d_in[3];     // [N, K2]
    float*       out  = (float*)d_out;           // [B, N, OUT]

    cudaFuncSetAttribute(conv_mma_pipe_kernel,
                         cudaFuncAttributeMaxDynamicSharedMemorySize, SM_TOTAL);
    conv_mma_pipe_kernel<<<GRID, NTHREADS, SM_TOTAL>>>(x, W, bias, k2, out);
}

// round 10
// speedup vs baseline: 1.2223x; 1.2223x over previous
#include <cuda_runtime.h>
#include <cuda_bf16.h>
#include <cstdint>
#include <cstddef>

// Problem constants
#define BB   64
#define NN   4096
#define CC   64
#define OUTF 64
#define K2   4
#define TM   128                       // sites per tile (GEMM M)
#define KDIM 256                       // GEMM K = K2*CC
#define NTILES 2048                    // BB * NN / TM
#define GRID 148
#define NTHREADS 512

#define ASTRB 528                      // row stride bytes (264 bf16; conflict-free ldmatrix)
#define ATILE (TM * ASTRB)             // 67584 bytes per (hi|lo) A tile

// smem layout (bytes)
#define SM_BIAS 0                      // 64 floats
#define SM_BHI  512                    // 64 rows * 528B = 33792
#define SM_BLO  (SM_BHI + OUTF * ASTRB)
#define SM_A    (SM_BLO + OUTF * ASTRB)     // hi tile, then lo tile
#define SM_TOTAL (SM_A + 2 * ATILE)         // 203264 bytes

// Pre-split x (set by prepass kernel): x = hi + lo, both bf16
__device__ __align__(128) __nv_bfloat16 g_xhi[BB * NN * CC];
__device__ __align__(128) __nv_bfloat16 g_xlo[BB * NN * CC];

__device__ __forceinline__ uint32_t smem_u32(const void* p) {
    uint32_t a;
    asm("{ .reg .u64 t; cvta.to.shared.u64 t, %1; cvt.u32.u64 %0, t; }" : "=r"(a) : "l"(p));
    return a;
}
__device__ __forceinline__ void ldsm_x4(uint32_t& r0, uint32_t& r1, uint32_t& r2, uint32_t& r3,
                                        uint32_t addr) {
    asm volatile("ldmatrix.sync.aligned.m8n8.x4.shared.b16 {%0,%1,%2,%3}, [%4];"
                 : "=r"(r0), "=r"(r1), "=r"(r2), "=r"(r3) : "r"(addr));
}
__device__ __forceinline__ void mma_bf16(float* acc, const uint32_t* a, const uint32_t* b) {
    asm volatile(
        "mma.sync.aligned.m16n8k16.row.col.f32.bf16.bf16.f32 "
        "{%0,%1,%2,%3}, {%4,%5,%6,%7}, {%8,%9}, {%0,%1,%2,%3};"
        : "+f"(acc[0]), "+f"(acc[1]), "+f"(acc[2]), "+f"(acc[3])
        : "r"(a[0]), "r"(a[1]), "r"(a[2]), "r"(a[3]), "r"(b[0]), "r"(b[1]));
}
__device__ __forceinline__ uint32_t pack_bf2(__nv_bfloat16 a, __nv_bfloat16 b) {
    __nv_bfloat162 t = __halves2bfloat162(a, b);
    uint32_t u;
    memcpy(&u, &t, 4);
    return u;
}
__device__ __forceinline__ void cp16(uint32_t dst, const void* src) {
    asm volatile("cp.async.cg.shared.global [%0], [%1], 16;" :: "r"(dst), "l"(src));
}

// ---- Prepass: split fp32 x into bf16 hi/lo arrays (memory-bound) ----
__global__ __launch_bounds__(1024, 2)
void split_kernel(const float* __restrict__ x)
{
    const int i = blockIdx.x * 1024 + threadIdx.x;     // float4 index, exact cover
    const float4 v = reinterpret_cast<const float4*>(x)[i];
    const __nv_bfloat16 h0 = __float2bfloat16(v.x);
    const __nv_bfloat16 h1 = __float2bfloat16(v.y);
    const __nv_bfloat16 h2 = __float2bfloat16(v.z);
    const __nv_bfloat16 h3 = __float2bfloat16(v.w);
    const __nv_bfloat16 l0 = __float2bfloat16(v.x - __bfloat162float(h0));
    const __nv_bfloat16 l1 = __float2bfloat16(v.y - __bfloat162float(h1));
    const __nv_bfloat16 l2 = __float2bfloat16(v.z - __bfloat162float(h2));
    const __nv_bfloat16 l3 = __float2bfloat16(v.w - __bfloat162float(h3));
    uint2 hv, lv;
    hv.x = pack_bf2(h0, h1);  hv.y = pack_bf2(h2, h3);
    lv.x = pack_bf2(l0, l1);  lv.y = pack_bf2(l2, l3);
    reinterpret_cast<uint2*>(g_xhi)[i] = hv;
    reinterpret_cast<uint2*>(g_xlo)[i] = lv;
}

__global__ __launch_bounds__(NTHREADS, 1)
void conv_mma_cpa_kernel(const float* __restrict__ W,
                         const float* __restrict__ bias,
                         const int*   __restrict__ kernel2,
                         float*       __restrict__ out)
{
    extern __shared__ char smem[];
    const uint32_t sbase = smem_u32(smem);
    const int tid  = threadIdx.x;
    const int wid  = tid >> 5;
    const int lane = tid & 31;
    const int wm   = wid & 3;          // warp M index: 4 groups of 32 rows
    const int wn   = wid >> 2;         // warp N index: 4 groups of 16 cols

    float* bias_s = reinterpret_cast<float*>(smem + SM_BIAS);
    if (tid < OUTF) bias_s[tid] = bias[tid];

    // ---- One-time: W split -> B_hi/B_lo smem, layout [o][kc] bf16, 528B stride ----
    for (int idx = tid; idx < OUTF * (KDIM / 2); idx += NTHREADS) {   // 8192 pairs
        const int o   = idx >> 7;
        const int kc0 = (idx & 127) << 1;
        const int k   = kc0 >> 6;
        const int c0  = kc0 & 63;
        const float* wp = W + k * (CC * OUTF) + c0 * OUTF + o;
        const float w0 = wp[0];
        const float w1 = wp[OUTF];
        const __nv_bfloat16 h0 = __float2bfloat16(w0);
        const __nv_bfloat16 h1 = __float2bfloat16(w1);
        const __nv_bfloat16 l0 = __float2bfloat16(w0 - __bfloat162float(h0));
        const __nv_bfloat16 l1 = __float2bfloat16(w1 - __bfloat162float(h1));
        const int off = o * ASTRB + kc0 * 2;
        *reinterpret_cast<uint32_t*>(smem + SM_BHI + off) = pack_bf2(h0, h1);
        *reinterpret_cast<uint32_t*>(smem + SM_BLO + off) = pack_bf2(l0, l1);
    }

    // ---- Tile-invariant ldmatrix per-lane addresses (identical to R8) ----
    const int m  = lane >> 3;
    const int l7 = lane & 7;
    const int a_row_off = ((m & 1) << 3) + l7;
    const int a_col_off = (m >> 1) << 4;
    const uint32_t aoff0 = (uint32_t)((wm * 32 + a_row_off) * ASTRB + a_col_off);
    const uint32_t aoff1 = aoff0 + 16 * ASTRB;
    const uint32_t ahi0 = sbase + SM_A + aoff0;
    const uint32_t ahi1 = sbase + SM_A + aoff1;
    const uint32_t alo0 = ahi0 + ATILE;
    const uint32_t alo1 = ahi1 + ATILE;
    const int b_row_off = ((m >> 1) << 3) + l7;
    const int b_col_off = (m & 1) << 4;
    const uint32_t boff = (uint32_t)((wn * 16 + b_row_off) * ASTRB + b_col_off);
    const uint32_t bhi = sbase + SM_BHI + boff;
    const uint32_t blo = sbase + SM_BLO + boff;

    // ---- Per-thread gather geometry: one (site,k) row per thread ----
    const int s_my = tid >> 2;         // site within tile (0..127)
    const int k_my = tid & 3;          // kernel tap
    const uint32_t adst_hi = sbase + SM_A + (uint32_t)(s_my * ASTRB + k_my * 128);
    const uint32_t adst_lo = adst_hi + ATILE;

    // ---- Prologue: cp.async-gather tile blockIdx.x ----
    int t = blockIdx.x;
    {
        const int b  = t >> 5;
        const int n0 = (t & 31) * TM;
        const int gi = __ldg(kernel2 + n0 * K2 + tid);
        const __nv_bfloat16* shi = g_xhi + ((size_t)b * NN + gi) * CC;
        const __nv_bfloat16* slo = g_xlo + ((size_t)b * NN + gi) * CC;
        #pragma unroll
        for (int c = 0; c < 8; ++c) cp16(adst_hi + c * 16, shi + c * 8);
        #pragma unroll
        for (int c = 0; c < 8; ++c) cp16(adst_lo + c * 16, slo + c * 8);
        asm volatile("cp.async.commit_group;" ::: "memory");
    }
    asm volatile("cp.async.wait_group 0;" ::: "memory");
    __syncthreads();

    // ---- Pipelined tile loop ----
    while (t < NTILES) {
        const int tn = t + GRID;
        const bool havenext = (tn < NTILES);

        // Prefetch next tile's gather index NOW (latency hidden under MMA)
        const __nv_bfloat16 *shi_n = nullptr, *slo_n = nullptr;
        if (havenext) {
            const int bn  = tn >> 5;
            const int n0n = (tn & 31) * TM;
            const int gin = __ldg(kernel2 + n0n * K2 + tid);
            shi_n = g_xhi + ((size_t)bn * NN + gin) * CC;
            slo_n = g_xlo + ((size_t)bn * NN + gin) * CC;
        }

        // -- MMA on A: Ahi*Bhi + Ahi*Blo + Alo*Bhi --
        float acc[2][2][4];
        #pragma unroll
        for (int i = 0; i < 2; ++i)
            #pragma unroll
            for (int j = 0; j < 2; ++j)
                #pragma unroll
                for (int q = 0; q < 4; ++q)
                    acc[i][j][q] = 0.0f;

        #pragma unroll 4
        for (int ks = 0; ks < 16; ++ks) {
            const uint32_t kb = (uint32_t)ks * 32;
            uint32_t AH[2][4], AL[2][4], BH[4], BL[4];
            ldsm_x4(AH[0][0], AH[0][1], AH[0][2], AH[0][3], ahi0 + kb);
            ldsm_x4(AH[1][0], AH[1][1], AH[1][2], AH[1][3], ahi1 + kb);
            ldsm_x4(AL[0][0], AL[0][1], AL[0][2], AL[0][3], alo0 + kb);
            ldsm_x4(AL[1][0], AL[1][1], AL[1][2], AL[1][3], alo1 + kb);
            ldsm_x4(BH[0], BH[1], BH[2], BH[3], bhi + kb);
            ldsm_x4(BL[0], BL[1], BL[2], BL[3], blo + kb);
            #pragma unroll
            for (int mi = 0; mi < 2; ++mi) {
                #pragma unroll
                for (int ni = 0; ni < 2; ++ni) {
                    mma_bf16(acc[mi][ni], AH[mi], BH + 2 * ni);
                    mma_bf16(acc[mi][ni], AH[mi], BL + 2 * ni);
                    mma_bf16(acc[mi][ni], AL[mi], BH + 2 * ni);
                }
            }
        }
        __syncthreads();   // all warps done reading A

        // -- Issue next tile's cp.async gather (overlaps epilogue) --
        if (havenext) {
            #pragma unroll
            for (int c = 0; c < 8; ++c) cp16(adst_hi + c * 16, shi_n + c * 8);
            #pragma unroll
            for (int c = 0; c < 8; ++c) cp16(adst_lo + c * 16, slo_n + c * 8);
            asm volatile("cp.async.commit_group;" ::: "memory");
        }

        // -- Epilogue: bias + store tile t --
        {
            const int b  = t >> 5;
            const int n0 = (t & 31) * TM;
            const size_t orow = (size_t)b * NN + n0 + wm * 32 + (lane >> 2);
            #pragma unroll
            for (int mi = 0; mi < 2; ++mi) {
                const size_t r0 = orow + mi * 16;
                #pragma unroll
                for (int ni = 0; ni < 2; ++ni) {
                    const int col = wn * 16 + ni * 8 + (lane & 3) * 2;
                    const float b0 = bias_s[col];
                    const float b1 = bias_s[col + 1];
                    float2 v0, v1;
                    v0.x = acc[mi][ni][0] + b0;  v0.y = acc[mi][ni][1] + b1;
                    v1.x = acc[mi][ni][2] + b0;  v1.y = acc[mi][ni][3] + b1;
                    *reinterpret_cast<float2*>(out + r0 * OUTF + col)       = v0;
                    *reinterpret_cast<float2*>(out + (r0 + 8) * OUTF + col) = v1;
                }
            }
        }

        asm volatile("cp.async.wait_group 0;" ::: "memory");
        __syncthreads();   // next tile's A visible to all warps
        t = tn;
    }
}

extern "C" void kernel_launch(void* const* d_in, const int* in_sizes, int n_in,
                              void* d_out, int out_size)
{
    const float* x    = (const float*)d_in[0];   // [B, N, C]
    const float* W    = (const float*)d_in[1];   // [K2, C, OUT]
    const float* bias = (const float*)d_in[2];   // [OUT]
    const int*   k2   = (const int*)d_in[3];     // [N, K2]
    float*       out  = (float*)d_out;           // [B, N, OUT]

    // Pass 1: split x into bf16 hi/lo (16.7M elems = 4.19M float4)
    split_kernel<<<4096, 1024>>>(x);

    // Pass 2: gathered GEMM
    cudaFuncSetAttribute(conv_mma_cpa_kernel,
                         cudaFuncAttributeMaxDynamicSharedMemorySize, SM_TOTAL);
    conv_mma_cpa_kernel<<<GRID, NTHREADS, SM_TOTAL>>>(W, bias, k2, out);
}

// round 11
// speedup vs baseline: 1.3634x; 1.1154x over previous
#include <cuda_runtime.h>
#include <cuda_bf16.h>
#include <cstdint>
#include <cstddef>

// Problem constants
#define BB   64
#define NN   4096
#define CC   64
#define OUTF 64
#define K2   4
#define TM   128                       // sites per tile (GEMM M)
#define KDIM 256                       // GEMM K = K2*CC
#define NTILES 2048                    // BB * NN / TM
#define GRID 148
#define NTHREADS 512

#define BSTRB 528                      // B row stride bytes (conflict-free ldmatrix)
#define ASTRB 272                      // A half-tile row stride bytes (128 kc * 2B + 16 pad; 17x16B -> conflict-free)
#define AHALF (TM * ASTRB)             // 34816 bytes per (hi|lo) half-K tile
#define ABUF  (2 * AHALF)              // 69632 bytes per buffer (hi + lo)

// smem layout (bytes)
#define SM_BIAS 0                      // 64 floats
#define SM_BHI  512                    // 64 rows * 528B = 33792
#define SM_BLO  (SM_BHI + OUTF * BSTRB)
#define SM_A0   (SM_BLO + OUTF * BSTRB)    // buffer 0: hi half-tile then lo half-tile
#define SM_A1   (SM_A0 + ABUF)             // buffer 1
#define SM_TOTAL (SM_A1 + ABUF)            // 207360 bytes

// Pre-split x (set by prepass kernel): x = hi + lo, both bf16
__device__ __align__(128) __nv_bfloat16 g_xhi[BB * NN * CC];
__device__ __align__(128) __nv_bfloat16 g_xlo[BB * NN * CC];

__device__ __forceinline__ uint32_t smem_u32(const void* p) {
    uint32_t a;
    asm("{ .reg .u64 t; cvta.to.shared.u64 t, %1; cvt.u32.u64 %0, t; }" : "=r"(a) : "l"(p));
    return a;
}
__device__ __forceinline__ void ldsm_x4(uint32_t& r0, uint32_t& r1, uint32_t& r2, uint32_t& r3,
                                        uint32_t addr) {
    asm volatile("ldmatrix.sync.aligned.m8n8.x4.shared.b16 {%0,%1,%2,%3}, [%4];"
                 : "=r"(r0), "=r"(r1), "=r"(r2), "=r"(r3) : "r"(addr));
}
__device__ __forceinline__ void mma_bf16(float* acc, const uint32_t* a, const uint32_t* b) {
    asm volatile(
        "mma.sync.aligned.m16n8k16.row.col.f32.bf16.bf16.f32 "
        "{%0,%1,%2,%3}, {%4,%5,%6,%7}, {%8,%9}, {%0,%1,%2,%3};"
        : "+f"(acc[0]), "+f"(acc[1]), "+f"(acc[2]), "+f"(acc[3])
        : "r"(a[0]), "r"(a[1]), "r"(a[2]), "r"(a[3]), "r"(b[0]), "r"(b[1]));
}
__device__ __forceinline__ uint32_t pack_bf2(__nv_bfloat16 a, __nv_bfloat16 b) {
    __nv_bfloat162 t = __halves2bfloat162(a, b);
    uint32_t u;
    memcpy(&u, &t, 4);
    return u;
}
__device__ __forceinline__ void cp16(uint32_t dst, const void* src) {
    asm volatile("cp.async.cg.shared.global [%0], [%1], 16;" :: "r"(dst), "l"(src));
}

// ---- Prepass: split fp32 x into bf16 hi/lo arrays (memory-bound) ----
__global__ __launch_bounds__(1024, 2)
void split_kernel(const float* __restrict__ x)
{
    const int i = blockIdx.x * 1024 + threadIdx.x;     // float4 index, exact cover
    const float4 v = reinterpret_cast<const float4*>(x)[i];
    const __nv_bfloat16 h0 = __float2bfloat16(v.x);
    const __nv_bfloat16 h1 = __float2bfloat16(v.y);
    const __nv_bfloat16 h2 = __float2bfloat16(v.z);
    const __nv_bfloat16 h3 = __float2bfloat16(v.w);
    const __nv_bfloat16 l0 = __float2bfloat16(v.x - __bfloat162float(h0));
    const __nv_bfloat16 l1 = __float2bfloat16(v.y - __bfloat162float(h1));
    const __nv_bfloat16 l2 = __float2bfloat16(v.z - __bfloat162float(h2));
    const __nv_bfloat16 l3 = __float2bfloat16(v.w - __bfloat162float(h3));
    uint2 hv, lv;
    hv.x = pack_bf2(h0, h1);  hv.y = pack_bf2(h2, h3);
    lv.x = pack_bf2(l0, l1);  lv.y = pack_bf2(l2, l3);
    reinterpret_cast<uint2*>(g_xhi)[i] = hv;
    reinterpret_cast<uint2*>(g_xlo)[i] = lv;
}

__global__ __launch_bounds__(NTHREADS, 1)
void conv_mma_pipe2_kernel(const float* __restrict__ W,
                           const float* __restrict__ bias,
                           const int*   __restrict__ kernel2,
                           float*       __restrict__ out)
{
    extern __shared__ char smem[];
    const uint32_t sbase = smem_u32(smem);
    const int tid  = threadIdx.x;
    const int wid  = tid >> 5;
    const int lane = tid & 31;
    const int wm   = wid & 3;          // warp M index: 4 groups of 32 rows
    const int wn   = wid >> 2;         // warp N index: 4 groups of 16 cols

    float* bias_s = reinterpret_cast<float*>(smem + SM_BIAS);
    if (tid < OUTF) bias_s[tid] = bias[tid];

    // ---- One-time: W split -> B_hi/B_lo smem, layout [o][kc] bf16, 528B stride ----
    for (int idx = tid; idx < OUTF * (KDIM / 2); idx += NTHREADS) {   // 8192 pairs
        const int o   = idx >> 7;
        const int kc0 = (idx & 127) << 1;
        const int k   = kc0 >> 6;
        const int c0  = kc0 & 63;
        const float* wp = W + k * (CC * OUTF) + c0 * OUTF + o;
        const float w0 = wp[0];
        const float w1 = wp[OUTF];
        const __nv_bfloat16 h0 = __float2bfloat16(w0);
        const __nv_bfloat16 h1 = __float2bfloat16(w1);
        const __nv_bfloat16 l0 = __float2bfloat16(w0 - __bfloat162float(h0));
        const __nv_bfloat16 l1 = __float2bfloat16(w1 - __bfloat162float(h1));
        const int off = o * BSTRB + kc0 * 2;
        *reinterpret_cast<uint32_t*>(smem + SM_BHI + off) = pack_bf2(h0, h1);
        *reinterpret_cast<uint32_t*>(smem + SM_BLO + off) = pack_bf2(l0, l1);
    }

    // ---- Tile-invariant ldmatrix per-lane addresses ----
    const int m  = lane >> 3;
    const int l7 = lane & 7;
    // A frags within a 272B-stride half-tile
    const uint32_t aoff0 = (uint32_t)((wm * 32 + ((m & 1) << 3) + l7) * ASTRB + ((m >> 1) << 4));
    const uint32_t aoff1 = aoff0 + 16 * ASTRB;
    // B frags (528B stride, full K)
    const uint32_t boff = (uint32_t)((wn * 16 + ((m >> 1) << 3) + l7) * BSTRB + ((m & 1) << 4));
    const uint32_t bhi = sbase + SM_BHI + boff;
    const uint32_t blo = sbase + SM_BLO + boff;

    // ---- Per-thread gather geometry ----
    // rid = tid>>1 in [0,256): s = rid>>1, kih = rid&1 (tap within half); p = tid&1 (64B part)
    const int p    = tid & 1;
    const int rid  = tid >> 1;
    const int s_my = rid >> 1;
    const int kih  = rid & 1;
    const uint32_t adst0 = sbase + SM_A0 + (uint32_t)(s_my * ASTRB + kih * 128 + p * 64);
    const uint32_t adst1 = adst0 + (SM_A1 - SM_A0);
    const int idx_off = s_my * 4 + kih;     // + n0*K2 + h*2

    // issue one half-gather (8x cp16 + commit): hi then lo
    auto issue_half = [&](uint32_t dsthi, int b, int gi) {
        const size_t rb = ((size_t)b * NN + gi) * CC + p * 32;
        const __nv_bfloat16* shi = g_xhi + rb;
        const __nv_bfloat16* slo = g_xlo + rb;
        #pragma unroll
        for (int c = 0; c < 4; ++c) cp16(dsthi + c * 16, shi + c * 8);
        #pragma unroll
        for (int c = 0; c < 4; ++c) cp16(dsthi + AHALF + c * 16, slo + c * 8);
        asm volatile("cp.async.commit_group;" ::: "memory");
    };

    // ---- Prologue: indices for tile t, start h0 -> buf0 ----
    int t = blockIdx.x;
    int b_cur  = t >> 5;
    int n0_cur = (t & 31) * TM;
    int gi_h0 = __ldg(kernel2 + n0_cur * K2 + idx_off);
    int gi_h1 = __ldg(kernel2 + n0_cur * K2 + idx_off + 2);
    issue_half(adst0, b_cur, gi_h0);

    while (t < NTILES) {
        const int tn = t + GRID;
        const bool havenext = (tn < NTILES);

        // issue h1 -> buf1   [pending: h0, h1]
        issue_half(adst1, b_cur, gi_h1);

        // prefetch next tile's indices (latency hidden under MMA h0)
        int b_n = 0, n0_n = 0, gi_h0n = 0, gi_h1n = 0;
        if (havenext) {
            b_n  = tn >> 5;
            n0_n = (tn & 31) * TM;
            gi_h0n = __ldg(kernel2 + n0_n * K2 + idx_off);
            gi_h1n = __ldg(kernel2 + n0_n * K2 + idx_off + 2);
        }

        // wait h0 (h1 stays in flight), sync, MMA on buf0 (ksteps 0..7)
        asm volatile("cp.async.wait_group 1;" ::: "memory");
        __syncthreads();

        float acc[2][2][4];
        #pragma unroll
        for (int i = 0; i < 2; ++i)
            #pragma unroll
            for (int j = 0; j < 2; ++j)
                #pragma unroll
                for (int q = 0; q < 4; ++q)
                    acc[i][j][q] = 0.0f;

        {
            const uint32_t ah0 = sbase + SM_A0 + aoff0;
            const uint32_t ah1 = sbase + SM_A0 + aoff1;
            #pragma unroll
            for (int ks = 0; ks < 8; ++ks) {
                const uint32_t ka = (uint32_t)ks * 32;          // A half-tile k offset
                const uint32_t kb = ka;                          // B k offset (half 0)
                uint32_t AH[2][4], AL[2][4], BH[4], BL[4];
                ldsm_x4(AH[0][0], AH[0][1], AH[0][2], AH[0][3], ah0 + ka);
                ldsm_x4(AH[1][0], AH[1][1], AH[1][2], AH[1][3], ah1 + ka);
                ldsm_x4(AL[0][0], AL[0][1], AL[0][2], AL[0][3], ah0 + AHALF + ka);
                ldsm_x4(AL[1][0], AL[1][1], AL[1][2], AL[1][3], ah1 + AHALF + ka);
                ldsm_x4(BH[0], BH[1], BH[2], BH[3], bhi + kb);
                ldsm_x4(BL[0], BL[1], BL[2], BL[3], blo + kb);
                #pragma unroll
                for (int mi = 0; mi < 2; ++mi)
                    #pragma unroll
                    for (int ni = 0; ni < 2; ++ni) {
                        mma_bf16(acc[mi][ni], AH[mi], BH + 2 * ni);
                        mma_bf16(acc[mi][ni], AH[mi], BL + 2 * ni);
                        mma_bf16(acc[mi][ni], AL[mi], BH + 2 * ni);
                    }
            }
        }
        __syncthreads();          // buf0 free

        // issue next tile's h0 -> buf0   [pending: h1, next.h0]
        if (havenext) issue_half(adst0, b_n, gi_h0n);

        // wait h1, sync, MMA on buf1 (ksteps 8..15)
        if (havenext) { asm volatile("cp.async.wait_group 1;" ::: "memory"); }
        else          { asm volatile("cp.async.wait_group 0;" ::: "memory"); }
        __syncthreads();

        {
            const uint32_t ah0 = sbase + SM_A1 + aoff0;
            const uint32_t ah1 = sbase + SM_A1 + aoff1;
            #pragma unroll
            for (int ks = 0; ks < 8; ++ks) {
                const uint32_t ka = (uint32_t)ks * 32;
                const uint32_t kb = ka + 256;                    // B k offset (half 1: +128 kc)
                uint32_t AH[2][4], AL[2][4], BH[4], BL[4];
                ldsm_x4(AH[0][0], AH[0][1], AH[0][2], AH[0][3], ah0 + ka);
                ldsm_x4(AH[1][0], AH[1][1], AH[1][2], AH[1][3], ah1 + ka);
                ldsm_x4(AL[0][0], AL[0][1], AL[0][2], AL[0][3], ah0 + AHALF + ka);
                ldsm_x4(AL[1][0], AL[1][1], AL[1][2], AL[1][3], ah1 + AHALF + ka);
                ldsm_x4(BH[0], BH[1], BH[2], BH[3], bhi + kb);
                ldsm_x4(BL[0], BL[1], BL[2], BL[3], blo + kb);
                #pragma unroll
                for (int mi = 0; mi < 2; ++mi)
                    #pragma unroll
                    for (int ni = 0; ni < 2; ++ni) {
                        mma_bf16(acc[mi][ni], AH[mi], BH + 2 * ni);
                        mma_bf16(acc[mi][ni], AH[mi], BL + 2 * ni);
                        mma_bf16(acc[mi][ni], AL[mi], BH + 2 * ni);
                    }
            }
        }

        // ---- Epilogue: bias + store tile t ----
        {
            const size_t orow = (size_t)b_cur * NN + n0_cur + wm * 32 + (lane >> 2);
            #pragma unroll
            for (int mi = 0; mi < 2; ++mi) {
                const size_t r0 = orow + mi * 16;
                #pragma unroll
                for (int ni = 0; ni < 2; ++ni) {
                    const int col = wn * 16 + ni * 8 + (lane & 3) * 2;
                    const float b0 = bias_s[col];
                    const float b1 = bias_s[col + 1];
                    float2 v0, v1;
                    v0.x = acc[mi][ni][0] + b0;  v0.y = acc[mi][ni][1] + b1;
                    v1.x = acc[mi][ni][2] + b0;  v1.y = acc[mi][ni][3] + b1;
                    *reinterpret_cast<float2*>(out + r0 * OUTF + col)       = v0;
                    *reinterpret_cast<float2*>(out + (r0 + 8) * OUTF + col) = v1;
                }
            }
        }

        __syncthreads();          // buf1 free before next iteration's h1 issue
        t = tn;
        b_cur = b_n;  n0_cur = n0_n;
        gi_h0 = gi_h0n;  gi_h1 = gi_h1n;
    }
}

extern "C" void kernel_launch(void* const* d_in, const int* in_sizes, int n_in,
                              void* d_out, int out_size)
{
    const float* x    = (const float*)d_in[0];   // [B, N, C]
    const float* W    = (const float*)d_in[1];   // [K2, C, OUT]
    const float* bias = (const float*)d_in[2];   // [OUT]
    const int*   k2   = (const int*)d_in[3];     // [N, K2]
    float*       out  = (float*)d_out;           // [B, N, OUT]

    // Pass 1: split x into bf16 hi/lo
    split_kernel<<<4096, 1024>>>(x);

    // Pass 2: half-K double-buffered gathered GEMM
    cudaFuncSetAttribute(conv_mma_pipe2_kernel,
                         cudaFuncAttributeMaxDynamicSharedMemorySize, SM_TOTAL);
    conv_mma_pipe2_kernel<<<GRID, NTHREADS, SM_TOTAL>>>(W, bias, k2, out);
}

// round 12
// speedup vs baseline: 1.9814x; 1.4532x over previous
#include <cuda_runtime.h>
#include <cuda_fp16.h>
#include <cstdint>
#include <cstddef>

// Problem constants
#define BB   64
#define NN   4096
#define CC   64
#define OUTF 64
#define K2   4
#define TM   128                       // sites per tile (GEMM M)
#define KDIM 256                       // GEMM K = K2*CC
#define NTILES 2048                    // BB * NN / TM
#define GRID 296                       // 2 CTAs per SM
#define NTHREADS 256

#define BSTRB 528                      // B row stride bytes (conflict-free ldmatrix)
#define ASTRB 272                      // A half-tile row stride bytes (128 kc * 2B + 16 pad)
#define AHALF (TM * ASTRB)             // 34816 bytes per half-K tile

// smem layout (bytes)
#define SM_BIAS 0                      // 64 floats
#define SM_B    512                    // 64 rows * 528B = 33792
#define SM_A0   (SM_B + OUTF * BSTRB)  // 34304
#define SM_A1   (SM_A0 + AHALF)        // 69120
#define SM_TOTAL (SM_A1 + AHALF)       // 103936 bytes -> 2 CTAs/SM

// Pre-converted x (fp16), set by prepass kernel
__device__ __align__(128) __half g_xh[BB * NN * CC];

__device__ __forceinline__ uint32_t smem_u32(const void* p) {
    uint32_t a;
    asm("{ .reg .u64 t; cvta.to.shared.u64 t, %1; cvt.u32.u64 %0, t; }" : "=r"(a) : "l"(p));
    return a;
}
__device__ __forceinline__ void ldsm_x4(uint32_t& r0, uint32_t& r1, uint32_t& r2, uint32_t& r3,
                                        uint32_t addr) {
    asm volatile("ldmatrix.sync.aligned.m8n8.x4.shared.b16 {%0,%1,%2,%3}, [%4];"
                 : "=r"(r0), "=r"(r1), "=r"(r2), "=r"(r3) : "r"(addr));
}
__device__ __forceinline__ void mma_fp16(float* acc, const uint32_t* a, const uint32_t* b) {
    asm volatile(
        "mma.sync.aligned.m16n8k16.row.col.f32.f16.f16.f32 "
        "{%0,%1,%2,%3}, {%4,%5,%6,%7}, {%8,%9}, {%0,%1,%2,%3};"
        : "+f"(acc[0]), "+f"(acc[1]), "+f"(acc[2]), "+f"(acc[3])
        : "r"(a[0]), "r"(a[1]), "r"(a[2]), "r"(a[3]), "r"(b[0]), "r"(b[1]));
}
__device__ __forceinline__ uint32_t pack_h2(float a, float b) {
    __half2 t = __floats2half2_rn(a, b);
    uint32_t u;
    memcpy(&u, &t, 4);
    return u;
}
__device__ __forceinline__ void cp16(uint32_t dst, const void* src) {
    asm volatile("cp.async.cg.shared.global [%0], [%1], 16;" :: "r"(dst), "l"(src));
}

// ---- Prepass: convert fp32 x to fp16 (memory-bound) ----
__global__ __launch_bounds__(1024, 2)
void tohalf_kernel(const float* __restrict__ x)
{
    const int i = blockIdx.x * 1024 + threadIdx.x;     // float4 index, exact cover
    const float4 v = reinterpret_cast<const float4*>(x)[i];
    uint2 hv;
    hv.x = pack_h2(v.x, v.y);
    hv.y = pack_h2(v.z, v.w);
    reinterpret_cast<uint2*>(g_xh)[i] = hv;
}

__global__ __launch_bounds__(NTHREADS, 2)
void conv_fp16_kernel(const float* __restrict__ W,
                      const float* __restrict__ bias,
                      const int*   __restrict__ kernel2,
                      float*       __restrict__ out)
{
    extern __shared__ char smem[];
    const uint32_t sbase = smem_u32(smem);
    const int tid  = threadIdx.x;
    const int wid  = tid >> 5;
    const int lane = tid & 31;
    const int wm   = wid & 3;          // warp M index: 4 groups of 32 rows
    const int wn   = wid >> 2;         // warp N index: 2 groups of 32 cols

    float* bias_s = reinterpret_cast<float*>(smem + SM_BIAS);
    if (tid < OUTF) bias_s[tid] = bias[tid];

    // ---- One-time: W -> fp16 B smem, layout [o][kc], 528B stride ----
    for (int idx = tid; idx < OUTF * (KDIM / 2); idx += NTHREADS) {   // 8192 pairs
        const int o   = idx >> 7;
        const int kc0 = (idx & 127) << 1;
        const int k   = kc0 >> 6;
        const int c0  = kc0 & 63;
        const float* wp = W + k * (CC * OUTF) + c0 * OUTF + o;
        *reinterpret_cast<uint32_t*>(smem + SM_B + o * BSTRB + kc0 * 2) =
            pack_h2(wp[0], wp[OUTF]);
    }

    // ---- Tile-invariant ldmatrix per-lane addresses ----
    const int m  = lane >> 3;
    const int l7 = lane & 7;
    // A frags within a 272B-stride half-tile (two m16 blocks of the warp's 32 rows)
    const uint32_t aoff0 = (uint32_t)((wm * 32 + ((m & 1) << 3) + l7) * ASTRB + ((m >> 1) << 4));
    const uint32_t aoff1 = aoff0 + 16 * ASTRB;
    // B frags: two n16 groups of the warp's 32 cols (528B stride, full K)
    const uint32_t boff0 = (uint32_t)((wn * 32 + ((m >> 1) << 3) + l7) * BSTRB + ((m & 1) << 4));
    const uint32_t boff1 = boff0 + 16 * BSTRB;
    const uint32_t bg0 = sbase + SM_B + boff0;
    const uint32_t bg1 = sbase + SM_B + boff1;

    // ---- Per-thread gather geometry: one (site, tap-in-half) row per thread ----
    const int s_my = tid >> 1;         // site within tile (0..127)
    const int kih  = tid & 1;          // tap within half
    const uint32_t adst0 = sbase + SM_A0 + (uint32_t)(s_my * ASTRB + kih * 128);
    const uint32_t adst1 = adst0 + (SM_A1 - SM_A0);
    const int idx_off = s_my * K2 + kih;     // + n0*K2, +2 for half 1

    // issue one half-gather: 8x cp16 (128B row) + commit
    auto issue_half = [&](uint32_t dst, int b, int gi) {
        const __half* src = g_xh + ((size_t)b * NN + gi) * CC;
        #pragma unroll
        for (int c = 0; c < 8; ++c) cp16(dst + c * 16, src + c * 8);
        asm volatile("cp.async.commit_group;" ::: "memory");
    };

    // ---- Prologue ----
    int t = blockIdx.x;
    int b_cur  = t >> 5;
    int n0_cur = (t & 31) * TM;
    int gi_h0 = 0, gi_h1 = 0;
    if (t < NTILES) {
        gi_h0 = __ldg(kernel2 + n0_cur * K2 + idx_off);
        gi_h1 = __ldg(kernel2 + n0_cur * K2 + idx_off + 2);
        issue_half(adst0, b_cur, gi_h0);
    }

    while (t < NTILES) {
        const int tn = t + GRID;
        const bool havenext = (tn < NTILES);

        // issue h1 -> buf1   [pending: h0, h1]
        issue_half(adst1, b_cur, gi_h1);

        // prefetch next tile's indices (hidden under MMA h0)
        int b_n = 0, n0_n = 0, gi_h0n = 0, gi_h1n = 0;
        if (havenext) {
            b_n  = tn >> 5;
            n0_n = (tn & 31) * TM;
            gi_h0n = __ldg(kernel2 + n0_n * K2 + idx_off);
            gi_h1n = __ldg(kernel2 + n0_n * K2 + idx_off + 2);
        }

        float acc[2][4][4];
        #pragma unroll
        for (int i = 0; i < 2; ++i)
            #pragma unroll
            for (int j = 0; j < 4; ++j)
                #pragma unroll
                for (int q = 0; q < 4; ++q)
                    acc[i][j][q] = 0.0f;

        // wait h0 (h1 in flight), sync, MMA on buf0 (ksteps 0..7)
        asm volatile("cp.async.wait_group 1;" ::: "memory");
        __syncthreads();
        {
            const uint32_t a0 = sbase + SM_A0 + aoff0;
            const uint32_t a1 = sbase + SM_A0 + aoff1;
            #pragma unroll
            for (int ks = 0; ks < 8; ++ks) {
                const uint32_t ka = (uint32_t)ks * 32;
                uint32_t A[2][4], B[2][4];
                ldsm_x4(A[0][0], A[0][1], A[0][2], A[0][3], a0 + ka);
                ldsm_x4(A[1][0], A[1][1], A[1][2], A[1][3], a1 + ka);
                ldsm_x4(B[0][0], B[0][1], B[0][2], B[0][3], bg0 + ka);
                ldsm_x4(B[1][0], B[1][1], B[1][2], B[1][3], bg1 + ka);
                #pragma unroll
                for (int mi = 0; mi < 2; ++mi)
                    #pragma unroll
                    for (int ni = 0; ni < 4; ++ni)
                        mma_fp16(acc[mi][ni], A[mi], B[ni >> 1] + 2 * (ni & 1));
            }
        }
        __syncthreads();          // buf0 free

        // issue next tile's h0 -> buf0   [pending: h1, next.h0]
        if (havenext) issue_half(adst0, b_n, gi_h0n);

        // wait h1, sync, MMA on buf1 (ksteps 8..15)
        if (havenext) { asm volatile("cp.async.wait_group 1;" ::: "memory"); }
        else          { asm volatile("cp.async.wait_group 0;" ::: "memory"); }
        __syncthreads();
        {
            const uint32_t a0 = sbase + SM_A1 + aoff0;
            const uint32_t a1 = sbase + SM_A1 + aoff1;
            #pragma unroll
            for (int ks = 0; ks < 8; ++ks) {
                const uint32_t ka = (uint32_t)ks * 32;
                const uint32_t kb = ka + 256;          // B k offset for kc 128..255
                uint32_t A[2][4], B[2][4];
                ldsm_x4(A[0][0], A[0][1], A[0][2], A[0][3], a0 + ka);
                ldsm_x4(A[1][0], A[1][1], A[1][2], A[1][3], a1 + ka);
                ldsm_x4(B[0][0], B[0][1], B[0][2], B[0][3], bg0 + kb);
                ldsm_x4(B[1][0], B[1][1], B[1][2], B[1][3], bg1 + kb);
                #pragma unroll
                for (int mi = 0; mi < 2; ++mi)
                    #pragma unroll
                    for (int ni = 0; ni < 4; ++ni)
                        mma_fp16(acc[mi][ni], A[mi], B[ni >> 1] + 2 * (ni & 1));
            }
        }

        // ---- Epilogue: bias + store tile t ----
        {
            const size_t orow = (size_t)b_cur * NN + n0_cur + wm * 32 + (lane >> 2);
            #pragma unroll
            for (int mi = 0; mi < 2; ++mi) {
                const size_t r0 = orow + mi * 16;
                #pragma unroll
                for (int ni = 0; ni < 4; ++ni) {
                    const int col = wn * 32 + ni * 8 + (lane & 3) * 2;
                    const float b0 = bias_s[col];
                    const float b1 = bias_s[col + 1];
                    float2 v0, v1;
                    v0.x = acc[mi][ni][0] + b0;  v0.y = acc[mi][ni][1] + b1;
                    v1.x = acc[mi][ni][2] + b0;  v1.y = acc[mi][ni][3] + b1;
                    *reinterpret_cast<float2*>(out + r0 * OUTF + col)       = v0;
                    *reinterpret_cast<float2*>(out + (r0 + 8) * OUTF + col) = v1;
                }
            }
        }

        __syncthreads();          // buf1 free before next iteration's h1 issue
        t = tn;
        b_cur = b_n;  n0_cur = n0_n;
        gi_h0 = gi_h0n;  gi_h1 = gi_h1n;
    }
}

extern "C" void kernel_launch(void* const* d_in, const int* in_sizes, int n_in,
                              void* d_out, int out_size)
{
    const float* x    = (const float*)d_in[0];   // [B, N, C]
    const float* W    = (const float*)d_in[1];   // [K2, C, OUT]
    const float* bias = (const float*)d_in[2];   // [OUT]
    const int*   k2   = (const int*)d_in[3];     // [N, K2]
    float*       out  = (float*)d_out;           // [B, N, OUT]

    // Pass 1: x -> fp16
    tohalf_kernel<<<4096, 1024>>>(x);

    // Pass 2: fp16 gathered GEMM, 2 CTAs/SM
    cudaFuncSetAttribute(conv_fp16_kernel,
                         cudaFuncAttributeMaxDynamicSharedMemorySize, SM_TOTAL);
    conv_fp16_kernel<<<GRID, NTHREADS, SM_TOTAL>>>(W, bias, k2, out);
}

// round 13
// speedup vs baseline: 2.1605x; 1.0904x over previous
#include <cuda_runtime.h>
#include <cuda_fp16.h>
#include <cstdint>
#include <cstddef>

// Problem constants
#define BB   64
#define NN   4096
#define CC   64
#define OUTF 64
#define K2   4
#define TM   128                       // sites per tile (GEMM M)
#define NTILES 2048                    // BB * NN / TM
#define GRID 296                       // 2 CTAs per SM
#define NTHREADS 256

#define BSTRB 528                      // B row stride bytes (conflict-free ldmatrix)
#define CHSTR 144                      // A chunk row stride bytes (64 kc * 2B + 16 pad; 36w%32=4 -> conflict-free)
#define ACH   (TM * CHSTR)             // 18432 bytes per chunk (one tap, 64 kc)

// smem layout (bytes)
#define SM_BIAS 0                      // 64 floats
#define SM_B    512                    // 64 rows * 528B = 33792
#define SM_A0   (SM_B + OUTF * BSTRB)  // 34304; 4 chunk buffers follow
#define SM_TOTAL (SM_A0 + 4 * ACH)     // 108032 bytes -> 2 CTAs/SM

// Pre-converted x (fp16), set by prepass kernel
__device__ __align__(128) __half g_xh[BB * NN * CC];

__device__ __forceinline__ uint32_t smem_u32(const void* p) {
    uint32_t a;
    asm("{ .reg .u64 t; cvta.to.shared.u64 t, %1; cvt.u32.u64 %0, t; }" : "=r"(a) : "l"(p));
    return a;
}
__device__ __forceinline__ void ldsm_x4(uint32_t& r0, uint32_t& r1, uint32_t& r2, uint32_t& r3,
                                        uint32_t addr) {
    asm volatile("ldmatrix.sync.aligned.m8n8.x4.shared.b16 {%0,%1,%2,%3}, [%4];"
                 : "=r"(r0), "=r"(r1), "=r"(r2), "=r"(r3) : "r"(addr));
}
__device__ __forceinline__ void mma_fp16(float* acc, const uint32_t* a, const uint32_t* b) {
    asm volatile(
        "mma.sync.aligned.m16n8k16.row.col.f32.f16.f16.f32 "
        "{%0,%1,%2,%3}, {%4,%5,%6,%7}, {%8,%9}, {%0,%1,%2,%3};"
        : "+f"(acc[0]), "+f"(acc[1]), "+f"(acc[2]), "+f"(acc[3])
        : "r"(a[0]), "r"(a[1]), "r"(a[2]), "r"(a[3]), "r"(b[0]), "r"(b[1]));
}
__device__ __forceinline__ uint32_t pack_h2(float a, float b) {
    __half2 t = __floats2half2_rn(a, b);
    uint32_t u;
    memcpy(&u, &t, 4);
    return u;
}
__device__ __forceinline__ void cp16(uint32_t dst, const void* src) {
    asm volatile("cp.async.cg.shared.global [%0], [%1], 16;" :: "r"(dst), "l"(src));
}
__device__ __forceinline__ void cp_commit() {
    asm volatile("cp.async.commit_group;" ::: "memory");
}
__device__ __forceinline__ void cp_wait2() {
    asm volatile("cp.async.wait_group 2;" ::: "memory");
}

// ---- Prepass: convert fp32 x to fp16 (memory-bound) ----
__global__ __launch_bounds__(1024, 2)
void tohalf_kernel(const float* __restrict__ x)
{
    const int i = blockIdx.x * 1024 + threadIdx.x;     // float4 index, exact cover
    const float4 v = reinterpret_cast<const float4*>(x)[i];
    uint2 hv;
    hv.x = pack_h2(v.x, v.y);
    hv.y = pack_h2(v.z, v.w);
    reinterpret_cast<uint2*>(g_xh)[i] = hv;
}

__global__ __launch_bounds__(NTHREADS, 2)
void conv_fp16_ring_kernel(const float* __restrict__ W,
                           const float* __restrict__ bias,
                           const int*   __restrict__ kernel2,
                           float*       __restrict__ out)
{
    extern __shared__ char smem[];
    const uint32_t sbase = smem_u32(smem);
    const int tid  = threadIdx.x;
    const int wid  = tid >> 5;
    const int lane = tid & 31;
    const int wm   = wid & 3;          // warp M index: 4 groups of 32 rows
    const int wn   = wid >> 2;         // warp N index: 2 groups of 32 cols

    float* bias_s = reinterpret_cast<float*>(smem + SM_BIAS);
    if (tid < OUTF) bias_s[tid] = bias[tid];

    // ---- One-time: W -> fp16 B smem, layout [o][kc], 528B stride ----
    for (int idx = tid; idx < OUTF * 128; idx += NTHREADS) {   // 8192 pairs (kc pairs)
        const int o   = idx >> 7;
        const int kc0 = (idx & 127) << 1;
        const int k   = kc0 >> 6;
        const int c0  = kc0 & 63;
        const float* wp = W + k * (CC * OUTF) + c0 * OUTF + o;
        *reinterpret_cast<uint32_t*>(smem + SM_B + o * BSTRB + kc0 * 2) =
            pack_h2(wp[0], wp[OUTF]);
    }

    // ---- Tile-invariant ldmatrix per-lane addresses ----
    const int m  = lane >> 3;
    const int l7 = lane & 7;
    // A frags within a 144B-stride chunk (two m16 blocks of the warp's 32 rows)
    const uint32_t aoff0 = (uint32_t)((wm * 32 + ((m & 1) << 3) + l7) * CHSTR + ((m >> 1) << 4));
    const uint32_t aoff1 = aoff0 + 16 * CHSTR;
    // B frags: two n16 groups of the warp's 32 cols (528B stride, full K)
    const uint32_t boff0 = (uint32_t)((wn * 32 + ((m >> 1) << 3) + l7) * BSTRB + ((m & 1) << 4));
    const uint32_t boff1 = boff0 + 16 * BSTRB;
    const uint32_t bg0 = sbase + SM_B + boff0;
    const uint32_t bg1 = sbase + SM_B + boff1;

    // ---- Per-thread gather geometry: half a row (64B) per thread ----
    const int s_my = tid >> 1;         // site within tile (0..127)
    const int p    = tid & 1;          // which 64B half of the 128B row
    const uint32_t adst = sbase + SM_A0 + (uint32_t)(s_my * CHSTR + p * 64);

    // issue one chunk gather (4x cp16 = 64B) + commit; buf == tap slot
    auto issue_chunk = [&](int buf, int b, int gi) {
        const uint32_t dst = adst + (uint32_t)buf * ACH;
        const __half* src = g_xh + ((size_t)b * NN + gi) * CC + p * 32;
        #pragma unroll
        for (int c = 0; c < 4; ++c) cp16(dst + c * 16, src + c * 8);
        cp_commit();
    };

    // MMA one chunk: buf j, B byte offset j*128 (64 kc)
    float acc[2][4][4];
    #pragma unroll
    for (int i = 0; i < 2; ++i)
        #pragma unroll
        for (int j = 0; j < 4; ++j)
            #pragma unroll
            for (int q = 0; q < 4; ++q)
                acc[i][j][q] = 0.0f;

    auto mma_chunk = [&](int buf, uint32_t koff) {
        const uint32_t a0 = sbase + SM_A0 + (uint32_t)buf * ACH + aoff0;
        const uint32_t a1 = sbase + SM_A0 + (uint32_t)buf * ACH + aoff1;
        #pragma unroll
        for (int ks = 0; ks < 4; ++ks) {
            const uint32_t ka = (uint32_t)ks * 32;
            uint32_t A[2][4], B[2][4];
            ldsm_x4(A[0][0], A[0][1], A[0][2], A[0][3], a0 + ka);
            ldsm_x4(A[1][0], A[1][1], A[1][2], A[1][3], a1 + ka);
            ldsm_x4(B[0][0], B[0][1], B[0][2], B[0][3], bg0 + koff + ka);
            ldsm_x4(B[1][0], B[1][1], B[1][2], B[1][3], bg1 + koff + ka);
            #pragma unroll
            for (int mi = 0; mi < 2; ++mi)
                #pragma unroll
                for (int ni = 0; ni < 4; ++ni)
                    mma_fp16(acc[mi][ni], A[mi], B[ni >> 1] + 2 * (ni & 1));
        }
    };

    // ---- Prologue: tile t0, issue taps 0,1,2 ----
    int t_cur  = blockIdx.x;                 // every CTA has >= 6 tiles
    int b_cur  = t_cur >> 5;
    int n0_cur = (t_cur & 31) * TM;
    int4 idxA = reinterpret_cast<const int4*>(kernel2)[n0_cur + s_my];
    issue_chunk(0, b_cur, idxA.x);
    issue_chunk(1, b_cur, idxA.y);
    issue_chunk(2, b_cur, idxA.z);

    // ---- Chunk-ring tile loop ----
    while (t_cur < NTILES) {
        const int t_nxt = t_cur + GRID;
        const bool havenext = (t_nxt < NTILES);
        const int b_nxt  = t_nxt >> 5;
        const int n0_nxt = (t_nxt & 31) * TM;

        // j=0: consume tap0; issue (t_cur, tap3)
        cp_wait2();
        __syncthreads();
        int4 idxB;
        if (havenext)
            idxB = reinterpret_cast<const int4*>(kernel2)[n0_nxt + s_my];
        issue_chunk(3, b_cur, idxA.w);
        mma_chunk(0, 0);

        // j=1: consume tap1; issue (t_nxt, tap0) into freed buf0
        cp_wait2();
        __syncthreads();
        if (havenext) issue_chunk(0, b_nxt, idxB.x); else cp_commit();
        mma_chunk(1, 128);

        // j=2: consume tap2; issue (t_nxt, tap1)
        cp_wait2();
        __syncthreads();
        if (havenext) issue_chunk(1, b_nxt, idxB.y); else cp_commit();
        mma_chunk(2, 256);

        // j=3: consume tap3; issue (t_nxt, tap2)
        cp_wait2();
        __syncthreads();
        if (havenext) issue_chunk(2, b_nxt, idxB.z); else cp_commit();
        mma_chunk(3, 384);

        // ---- Epilogue: bias + store tile t_cur; reset accumulators ----
        {
            const size_t orow = (size_t)b_cur * NN + n0_cur + wm * 32 + (lane >> 2);
            #pragma unroll
            for (int mi = 0; mi < 2; ++mi) {
                const size_t r0 = orow + mi * 16;
                #pragma unroll
                for (int ni = 0; ni < 4; ++ni) {
                    const int col = wn * 32 + ni * 8 + (lane & 3) * 2;
                    const float b0 = bias_s[col];
                    const float b1 = bias_s[col + 1];
                    float2 v0, v1;
                    v0.x = acc[mi][ni][0] + b0;  v0.y = acc[mi][ni][1] + b1;
                    v1.x = acc[mi][ni][2] + b0;  v1.y = acc[mi][ni][3] + b1;
                    *reinterpret_cast<float2*>(out + r0 * OUTF + col)       = v0;
                    *reinterpret_cast<float2*>(out + (r0 + 8) * OUTF + col) = v1;
                    acc[mi][ni][0] = 0.0f; acc[mi][ni][1] = 0.0f;
                    acc[mi][ni][2] = 0.0f; acc[mi][ni][3] = 0.0f;
                }
            }
        }

        t_cur = t_nxt;  b_cur = b_nxt;  n0_cur = n0_nxt;
        idxA = idxB;
    }
}

extern "C" void kernel_launch(void* const* d_in, const int* in_sizes, int n_in,
                              void* d_out, int out_size)
{
    const float* x    = (const float*)d_in[0];   // [B, N, C]
    const float* W    = (const float*)d_in[1];   // [K2, C, OUT]
    const float* bias = (const float*)d_in[2];   // [OUT]
    const int*   k2   = (const int*)d_in[3];     // [N, K2]
    float*       out  = (float*)d_out;           // [B, N, OUT]

    // Pass 1: x -> fp16
    tohalf_kernel<<<4096, 1024>>>(x);

    // Pass 2: fp16 gathered GEMM, 4-deep chunk ring, 2 CTAs/SM
    cudaFuncSetAttribute(conv_fp16_ring_kernel,
                         cudaFuncAttributeMaxDynamicSharedMemorySize, SM_TOTAL);
    conv_fp16_ring_kernel<<<GRID, NTHREADS, SM_TOTAL>>>(W, bias, k2, out);
}

// round 14
// speedup vs baseline: 2.2748x; 1.0529x over previous
#include <cuda_runtime.h>
#include <cuda_fp16.h>
#include <cstdint>
#include <cstddef>

// Problem constants
#define BB   64
#define NN   4096
#define CC   64
#define OUTF 64
#define K2   4
#define TM   128                       // sites per tile (GEMM M)
#define NTILES 2048                    // BB * NN / TM
#define GRID 296                       // 2 CTAs per SM
#define NTHREADS 256

#define BSTRB 528                      // B row stride bytes (conflict-free ldmatrix)
#define CHSTR 144                      // A chunk row stride bytes (64 kc * 2B + 16 pad)
#define WCH   (16 * CHSTR)             // 2304 B: one warp-chunk (16 sites x 64 kc)

// smem layout (bytes)
#define SM_BIAS 0                      // 64 floats
#define SM_B    512                    // 64 rows * 528B = 33792
#define SM_A0   (SM_B + OUTF * BSTRB)  // 34304; then [warp][buf] chunk ring
#define SM_TOTAL (SM_A0 + 8 * 4 * WCH) // 108032 bytes -> 2 CTAs/SM

// Pre-converted x (fp16), set by prepass kernel
__device__ __align__(128) __half g_xh[BB * NN * CC];

__device__ __forceinline__ uint32_t smem_u32(const void* p) {
    uint32_t a;
    asm("{ .reg .u64 t; cvta.to.shared.u64 t, %1; cvt.u32.u64 %0, t; }" : "=r"(a) : "l"(p));
    return a;
}
__device__ __forceinline__ void ldsm_x4(uint32_t& r0, uint32_t& r1, uint32_t& r2, uint32_t& r3,
                                        uint32_t addr) {
    asm volatile("ldmatrix.sync.aligned.m8n8.x4.shared.b16 {%0,%1,%2,%3}, [%4];"
                 : "=r"(r0), "=r"(r1), "=r"(r2), "=r"(r3) : "r"(addr));
}
__device__ __forceinline__ void mma_fp16(float* acc, const uint32_t* a, const uint32_t* b) {
    asm volatile(
        "mma.sync.aligned.m16n8k16.row.col.f32.f16.f16.f32 "
        "{%0,%1,%2,%3}, {%4,%5,%6,%7}, {%8,%9}, {%0,%1,%2,%3};"
        : "+f"(acc[0]), "+f"(acc[1]), "+f"(acc[2]), "+f"(acc[3])
        : "r"(a[0]), "r"(a[1]), "r"(a[2]), "r"(a[3]), "r"(b[0]), "r"(b[1]));
}
__device__ __forceinline__ uint32_t pack_h2(float a, float b) {
    __half2 t = __floats2half2_rn(a, b);
    uint32_t u;
    memcpy(&u, &t, 4);
    return u;
}
__device__ __forceinline__ void cp16(uint32_t dst, const void* src) {
    asm volatile("cp.async.cg.shared.global [%0], [%1], 16;" :: "r"(dst), "l"(src));
}
__device__ __forceinline__ void cp_commit() {
    asm volatile("cp.async.commit_group;" ::: "memory");
}
__device__ __forceinline__ void cp_wait2() {
    asm volatile("cp.async.wait_group 2;" ::: "memory");
}

// ---- Prepass: convert fp32 x to fp16 (memory-bound) ----
__global__ __launch_bounds__(1024, 2)
void tohalf_kernel(const float* __restrict__ x)
{
    const int i = blockIdx.x * 1024 + threadIdx.x;     // float4 index, exact cover
    const float4 v = reinterpret_cast<const float4*>(x)[i];
    uint2 hv;
    hv.x = pack_h2(v.x, v.y);
    hv.y = pack_h2(v.z, v.w);
    reinterpret_cast<uint2*>(g_xh)[i] = hv;
}

__global__ __launch_bounds__(NTHREADS, 2)
void conv_fp16_wp_kernel(const float* __restrict__ W,
                         const float* __restrict__ bias,
                         const int*   __restrict__ kernel2,
                         float*       __restrict__ out)
{
    extern __shared__ char smem[];
    const uint32_t sbase = smem_u32(smem);
    const int tid  = threadIdx.x;
    const int wid  = tid >> 5;         // warp owns sites [wid*16, wid*16+16)
    const int lane = tid & 31;

    float* bias_s = reinterpret_cast<float*>(smem + SM_BIAS);
    if (tid < OUTF) bias_s[tid] = bias[tid];

    // ---- One-time: W -> fp16 B smem, layout [o][kc], 528B stride ----
    for (int idx = tid; idx < OUTF * 128; idx += NTHREADS) {   // 8192 kc-pairs
        const int o   = idx >> 7;
        const int kc0 = (idx & 127) << 1;
        const int k   = kc0 >> 6;
        const int c0  = kc0 & 63;
        const float* wp = W + k * (CC * OUTF) + c0 * OUTF + o;
        *reinterpret_cast<uint32_t*>(smem + SM_B + o * BSTRB + kc0 * 2) =
            pack_h2(wp[0], wp[OUTF]);
    }

    // ---- Tile-invariant ldmatrix per-lane addresses ----
    const int m  = lane >> 3;          // matrix index 0..3
    const int l7 = lane & 7;
    // A (warp-private 16-row chunk, 144B stride): one m16 block
    const uint32_t aoff = (uint32_t)((((m & 1) << 3) + l7) * CHSTR + ((m >> 1) << 4));
    // B: 4 n16 groups covering all 64 cols
    uint32_t bg[4];
    #pragma unroll
    for (int g = 0; g < 4; ++g)
        bg[g] = sbase + SM_B +
                (uint32_t)((g * 16 + ((m >> 1) << 3) + l7) * BSTRB + ((m & 1) << 4));

    // ---- Warp-private gather geometry ----
    const int s_loc = lane >> 1;       // site within warp's 16
    const int p     = lane & 1;        // 64B half of the 128B row
    const uint32_t warpA = sbase + SM_A0 + (uint32_t)(wid * 4 * WCH);
    const uint32_t adst  = warpA + (uint32_t)(s_loc * CHSTR + p * 64);

    // issue one warp-chunk gather (this thread's 64B) + commit
    auto issue_chunk = [&](int buf, int b, int gi) {
        const uint32_t dst = adst + (uint32_t)buf * WCH;
        const __half* src = g_xh + ((size_t)b * NN + gi) * CC + p * 32;
        #pragma unroll
        for (int c = 0; c < 4; ++c) cp16(dst + c * 16, src + c * 8);
        cp_commit();
    };

    float acc[8][4];
    #pragma unroll
    for (int i = 0; i < 8; ++i)
        #pragma unroll
        for (int q = 0; q < 4; ++q)
            acc[i][q] = 0.0f;

    // MMA one chunk: buf j, B byte offset koff = j*128 (64 kc)
    auto mma_chunk = [&](int buf, uint32_t koff) {
        const uint32_t a0 = warpA + (uint32_t)buf * WCH + aoff;
        #pragma unroll
        for (int ks = 0; ks < 4; ++ks) {
            const uint32_t ka = (uint32_t)ks * 32;
            uint32_t A[4], B[4][4];
            ldsm_x4(A[0], A[1], A[2], A[3], a0 + ka);
            #pragma unroll
            for (int g = 0; g < 4; ++g)
                ldsm_x4(B[g][0], B[g][1], B[g][2], B[g][3], bg[g] + koff + ka);
            #pragma unroll
            for (int g = 0; g < 4; ++g) {
                mma_fp16(acc[2 * g],     A, B[g] + 0);
                mma_fp16(acc[2 * g + 1], A, B[g] + 2);
            }
        }
    };

    // ---- Prologue: tile t0, issue taps 0,1,2 (warp-local) ----
    int t_cur  = blockIdx.x;
    int b_cur  = t_cur >> 5;
    int n0_cur = (t_cur & 31) * TM;
    int4 idxA = reinterpret_cast<const int4*>(kernel2)[n0_cur + wid * 16 + s_loc];
    issue_chunk(0, b_cur, idxA.x);
    issue_chunk(1, b_cur, idxA.y);
    issue_chunk(2, b_cur, idxA.z);
    __syncthreads();                   // B + bias visible to all warps

    // ---- Barrier-free warp-private tile loop ----
    while (t_cur < NTILES) {
        const int t_nxt = t_cur + GRID;
        const bool havenext = (t_nxt < NTILES);
        const int b_nxt  = t_nxt >> 5;
        const int n0_nxt = (t_nxt & 31) * TM;

        // prefetch next tile's indices (covered by MMA below)
        int4 idxB = idxA;
        if (havenext)
            idxB = reinterpret_cast<const int4*>(kernel2)[n0_nxt + wid * 16 + s_loc];

        // j=0: consume tap0; issue (t_cur, tap3)
        cp_wait2();  __syncwarp();
        issue_chunk(3, b_cur, idxA.w);
        mma_chunk(0, 0);

        // j=1: consume tap1; refill buf0 with (t_nxt, tap0)
        cp_wait2();  __syncwarp();
        if (havenext) issue_chunk(0, b_nxt, idxB.x); else cp_commit();
        mma_chunk(1, 128);

        // j=2: consume tap2; refill buf1
        cp_wait2();  __syncwarp();
        if (havenext) issue_chunk(1, b_nxt, idxB.y); else cp_commit();
        mma_chunk(2, 256);

        // j=3: consume tap3; refill buf2
        cp_wait2();  __syncwarp();
        if (havenext) issue_chunk(2, b_nxt, idxB.z); else cp_commit();
        mma_chunk(3, 384);

        // ---- Epilogue: bias + store warp's 16 rows x 64 cols; reset acc ----
        {
            const size_t orow = (size_t)b_cur * NN + n0_cur + wid * 16 + (lane >> 2);
            #pragma unroll
            for (int nb = 0; nb < 8; ++nb) {
                const int col = nb * 8 + (lane & 3) * 2;
                const float b0 = bias_s[col];
                const float b1 = bias_s[col + 1];
                float2 v0, v1;
                v0.x = acc[nb][0] + b0;  v0.y = acc[nb][1] + b1;
                v1.x = acc[nb][2] + b0;  v1.y = acc[nb][3] + b1;
                *reinterpret_cast<float2*>(out + orow * OUTF + col)       = v0;
                *reinterpret_cast<float2*>(out + (orow + 8) * OUTF + col) = v1;
                acc[nb][0] = 0.0f; acc[nb][1] = 0.0f;
                acc[nb][2] = 0.0f; acc[nb][3] = 0.0f;
            }
        }

        t_cur = t_nxt;  b_cur = b_nxt;  n0_cur = n0_nxt;
        idxA = idxB;
    }
}

extern "C" void kernel_launch(void* const* d_in, const int* in_sizes, int n_in,
                              void* d_out, int out_size)
{
    const float* x    = (const float*)d_in[0];   // [B, N, C]
    const float* W    = (const float*)d_in[1];   // [K2, C, OUT]
    const float* bias = (const float*)d_in[2];   // [OUT]
    const int*   k2   = (const int*)d_in[3];     // [N, K2]
    float*       out  = (float*)d_out;           // [B, N, OUT]

    // Pass 1: x -> fp16
    tohalf_kernel<<<4096, 1024>>>(x);

    // Pass 2: fp16 gathered GEMM, warp-private chunk rings, no block barriers
    cudaFuncSetAttribute(conv_fp16_wp_kernel,
                         cudaFuncAttributeMaxDynamicSharedMemorySize, SM_TOTAL);
    conv_fp16_wp_kernel<<<GRID, NTHREADS, SM_TOTAL>>>(W, bias, k2, out);
}

// round 16
// speedup vs baseline: 2.4382x; 1.0718x over previous
#include <cuda_runtime.h>
#include <cuda_fp16.h>
#include <cstdint>
#include <cstddef>

// Problem constants
#define BB   64
#define NN   4096
#define CC   64
#define OUTF 64
#define K2   4
#define TM   128                       // sites per tile (GEMM M)
#define NTILES 2048                    // BB * NN / TM
#define GRID 296                       // 2 CTAs per SM
#define NTHREADS 256

#define BSTRB 528                      // B row stride bytes (conflict-free ldmatrix)
#define CHSTR 144                      // A chunk row stride bytes (64 kc * 2B + 16 pad)
#define WCH   (16 * CHSTR)             // 2304 B: one warp-chunk (16 sites x 64 kc)

// smem layout (bytes)
#define SM_BIAS 0                      // 64 floats
#define SM_MBAR 256                    // 8 warps * 4 bufs * 8B = 256B
#define SM_B    512                    // 64 rows * 528B = 33792
#define SM_A0   (SM_B + OUTF * BSTRB)  // 34304; then [warp][buf] chunk ring
#define SM_TOTAL (SM_A0 + 8 * 4 * WCH) // 108032 bytes -> 2 CTAs/SM

// Pre-converted x (fp16), set by prepass kernel
__device__ __align__(128) __half g_xh[BB * NN * CC];

__device__ __forceinline__ uint32_t smem_u32(const void* p) {
    uint32_t a;
    asm("{ .reg .u64 t; cvta.to.shared.u64 t, %1; cvt.u32.u64 %0, t; }" : "=r"(a) : "l"(p));
    return a;
}
__device__ __forceinline__ void ldsm_x4(uint32_t& r0, uint32_t& r1, uint32_t& r2, uint32_t& r3,
                                        uint32_t addr) {
    asm volatile("ldmatrix.sync.aligned.m8n8.x4.shared.b16 {%0,%1,%2,%3}, [%4];"
                 : "=r"(r0), "=r"(r1), "=r"(r2), "=r"(r3) : "r"(addr));
}
__device__ __forceinline__ void mma_fp16(float* acc, const uint32_t* a, const uint32_t* b) {
    asm volatile(
        "mma.sync.aligned.m16n8k16.row.col.f32.f16.f16.f32 "
        "{%0,%1,%2,%3}, {%4,%5,%6,%7}, {%8,%9}, {%0,%1,%2,%3};"
        : "+f"(acc[0]), "+f"(acc[1]), "+f"(acc[2]), "+f"(acc[3])
        : "r"(a[0]), "r"(a[1]), "r"(a[2]), "r"(a[3]), "r"(b[0]), "r"(b[1]));
}
__device__ __forceinline__ uint32_t pack_h2(float a, float b) {
    __half2 t = __floats2half2_rn(a, b);
    uint32_t u;
    memcpy(&u, &t, 4);
    return u;
}
__device__ __forceinline__ void mbar_wait(uint32_t mbar, uint32_t parity) {
    asm volatile(
        "{\n\t.reg .pred P1;\n\t"
        "WAIT_LOOP_%=:\n\t"
        "mbarrier.try_wait.parity.acquire.cta.shared::cta.b64 P1, [%0], %1, 0x989680;\n\t"
        "@P1 bra.uni WAIT_DONE_%=;\n\t"
        "bra.uni WAIT_LOOP_%=;\n\t"
        "WAIT_DONE_%=:\n\t}"
        :: "r"(mbar), "r"(parity) : "memory");
}

// ---- Prepass: convert fp32 x to fp16 (memory-bound) ----
__global__ __launch_bounds__(1024, 2)
void tohalf_kernel(const float* __restrict__ x)
{
    const int i = blockIdx.x * 1024 + threadIdx.x;     // float4 index, exact cover
    const float4 v = reinterpret_cast<const float4*>(x)[i];
    uint2 hv;
    hv.x = pack_h2(v.x, v.y);
    hv.y = pack_h2(v.z, v.w);
    reinterpret_cast<uint2*>(g_xh)[i] = hv;
}

__global__ __launch_bounds__(NTHREADS, 2)
void conv_fp16_blk_kernel(const float* __restrict__ W,
                          const float* __restrict__ bias,
                          const int*   __restrict__ kernel2,
                          float*       __restrict__ out)
{
    extern __shared__ char smem[];
    const uint32_t sbase = smem_u32(smem);
    const int tid  = threadIdx.x;
    const int wid  = tid >> 5;         // warp owns sites [wid*16, wid*16+16)
    const int lane = tid & 31;

    float* bias_s = reinterpret_cast<float*>(smem + SM_BIAS);
    if (tid < OUTF) bias_s[tid] = bias[tid];

    // ---- mbarrier init: one per (warp, buf) ----
    if (tid == 0) {
        #pragma unroll
        for (int i = 0; i < 32; ++i)
            asm volatile("mbarrier.init.shared.b64 [%0], %1;"
                         :: "r"(sbase + SM_MBAR + i * 8), "r"(1u) : "memory");
    }

    // ---- One-time: W -> fp16 B smem, layout [o][kc], 528B stride ----
    for (int idx = tid; idx < OUTF * 128; idx += NTHREADS) {   // 8192 kc-pairs
        const int o   = idx >> 7;
        const int kc0 = (idx & 127) << 1;
        const int k   = kc0 >> 6;
        const int c0  = kc0 & 63;
        const float* wp = W + k * (CC * OUTF) + c0 * OUTF + o;
        *reinterpret_cast<uint32_t*>(smem + SM_B + o * BSTRB + kc0 * 2) =
            pack_h2(wp[0], wp[OUTF]);
    }
    __syncthreads();                   // mbars + B + bias ready

    // ---- Tile-invariant ldmatrix per-lane addresses ----
    const int m  = lane >> 3;
    const int l7 = lane & 7;
    // A (warp-private 16-row chunk, 144B stride): one m16 block
    const uint32_t aoff = (uint32_t)((((m & 1) << 3) + l7) * CHSTR + ((m >> 1) << 4));
    // B: 4 n16 groups covering all 64 cols
    uint32_t bg[4];
    #pragma unroll
    for (int g = 0; g < 4; ++g)
        bg[g] = sbase + SM_B +
                (uint32_t)((g * 16 + ((m >> 1) << 3) + l7) * BSTRB + ((m & 1) << 4));

    const uint32_t warpA   = sbase + SM_A0 + (uint32_t)(wid * 4 * WCH);
    const uint32_t mb_base = sbase + SM_MBAR + (uint32_t)(wid * 4 * 8);
    const int      sl      = lane & 15;          // site handled by this lane (dup 16-31)

    // issue one warp-chunk gather: expect_tx + 16 x 128B bulk copies (lanes 0..15)
    auto issue_chunk = [&](int buf, int b, int gi_lane) {
        const uint32_t mbar = mb_base + (uint32_t)(buf * 8);
        if (lane == 0)
            asm volatile("mbarrier.arrive.expect_tx.shared.b64 _, [%0], %1;"
                         :: "r"(mbar), "r"(2048u) : "memory");
        if (lane < 16) {
            const uint32_t dst = warpA + (uint32_t)buf * WCH + (uint32_t)(lane * CHSTR);
            const __half* src = g_xh + ((size_t)b * NN + gi_lane) * CC;   // 128B row
            asm volatile(
                "cp.async.bulk.shared::cta.global.mbarrier::complete_tx::bytes "
                "[%0], [%1], 128, [%2];"
                :: "r"(dst), "l"(src), "r"(mbar) : "memory");
        }
    };

    float acc[8][4];
    #pragma unroll
    for (int i = 0; i < 8; ++i)
        #pragma unroll
        for (int q = 0; q < 4; ++q)
            acc[i][q] = 0.0f;

    // MMA one chunk: buf j, B byte offset koff = j*128 (64 kc)
    auto mma_chunk = [&](int buf, uint32_t koff) {
        const uint32_t a0 = warpA + (uint32_t)buf * WCH + aoff;
        #pragma unroll
        for (int ks = 0; ks < 4; ++ks) {
            const uint32_t ka = (uint32_t)ks * 32;
            uint32_t A[4], B[4][4];
            ldsm_x4(A[0], A[1], A[2], A[3], a0 + ka);
            #pragma unroll
            for (int g = 0; g < 4; ++g)
                ldsm_x4(B[g][0], B[g][1], B[g][2], B[g][3], bg[g] + koff + ka);
            #pragma unroll
            for (int g = 0; g < 4; ++g) {
                mma_fp16(acc[2 * g],     A, B[g] + 0);
                mma_fp16(acc[2 * g + 1], A, B[g] + 2);
            }
        }
    };

    // ---- Prologue: tile t0, issue taps 0,1,2 (warp-local) ----
    int t_cur  = blockIdx.x;
    int b_cur  = t_cur >> 5;
    int n0_cur = (t_cur & 31) * TM;
    int4 idxA = reinterpret_cast<const int4*>(kernel2)[n0_cur + wid * 16 + sl];
    issue_chunk(0, b_cur, idxA.x);
    issue_chunk(1, b_cur, idxA.y);
    issue_chunk(2, b_cur, idxA.z);

    uint32_t par = 0;                  // parity bit per buffer

    // ---- Barrier-free warp-private tile loop ----
    while (t_cur < NTILES) {
        const int t_nxt = t_cur + GRID;
        const bool havenext = (t_nxt < NTILES);
        const int b_nxt  = t_nxt >> 5;
        const int n0_nxt = (t_nxt & 31) * TM;

        // prefetch next tile's indices (covered by MMA below)
        int4 idxB = idxA;
        if (havenext)
            idxB = reinterpret_cast<const int4*>(kernel2)[n0_nxt + wid * 16 + sl];

        // j=0: consume tap0; issue (t_cur, tap3) -> buf3
        mbar_wait(mb_base + 0, par & 1);  __syncwarp();
        issue_chunk(3, b_cur, idxA.w);
        mma_chunk(0, 0);

        // j=1: consume tap1; refill buf0 with (t_nxt, tap0)
        mbar_wait(mb_base + 8, (par >> 1) & 1);  __syncwarp();
        if (havenext) issue_chunk(0, b_nxt, idxB.x);
        mma_chunk(1, 128);

        // j=2: consume tap2; refill buf1
        mbar_wait(mb_base + 16, (par >> 2) & 1);  __syncwarp();
        if (havenext) issue_chunk(1, b_nxt, idxB.y);
        mma_chunk(2, 256);

        // j=3: consume tap3; refill buf2
        mbar_wait(mb_base + 24, (par >> 3) & 1);  __syncwarp();
        if (havenext) issue_chunk(2, b_nxt, idxB.z);
        mma_chunk(3, 384);

        par ^= 0xF;                    // all four buffers flipped phase this tile

        // ---- Epilogue: bias + store warp's 16 rows x 64 cols; reset acc ----
        {
            const size_t orow = (size_t)b_cur * NN + n0_cur + wid * 16 + (lane >> 2);
            #pragma unroll
            for (int nb = 0; nb < 8; ++nb) {
                const int col = nb * 8 + (lane & 3) * 2;
                const float b0 = bias_s[col];
                const float b1 = bias_s[col + 1];
                float2 v0, v1;
                v0.x = acc[nb][0] + b0;  v0.y = acc[nb][1] + b1;
                v1.x = acc[nb][2] + b0;  v1.y = acc[nb][3] + b1;
                *reinterpret_cast<float2*>(out + orow * OUTF + col)       = v0;
                *reinterpret_cast<float2*>(out + (orow + 8) * OUTF + col) = v1;
                acc[nb][0] = 0.0f; acc[nb][1] = 0.0f;
                acc[nb][2] = 0.0f; acc[nb][3] = 0.0f;
            }
        }

        t_cur = t_nxt;  b_cur = b_nxt;  n0_cur = n0_nxt;
        idxA = idxB;
    }
}

extern "C" void kernel_launch(void* const* d_in, const int* in_sizes, int n_in,
                              void* d_out, int out_size)
{
    const float* x    = (const float*)d_in[0];   // [B, N, C]
    const float* W    = (const float*)d_in[1];   // [K2, C, OUT]
    const float* bias = (const float*)d_in[2];   // [OUT]
    const int*   k2   = (const int*)d_in[3];     // [N, K2]
    float*       out  = (float*)d_out;           // [B, N, OUT]

    // Pass 1: x -> fp16
    tohalf_kernel<<<4096, 1024>>>(x);

    // Pass 2: fp16 gathered GEMM, cp.async.bulk gather, warp-private rings
    cudaFuncSetAttribute(conv_fp16_blk_kernel,
                         cudaFuncAttributeMaxDynamicSharedMemorySize, SM_TOTAL);
    conv_fp16_blk_kernel<<<GRID, NTHREADS, SM_TOTAL>>>(W, bias, k2, out);
}